// round 5
// baseline (speedup 1.0000x reference)
#include <cuda_runtime.h>
#include <cstdint>

#define BATCH 8
#define NPTS  8192
#define MCEN  2048
#define KNBR  32
#define CFEAT 64
#define CINF  67
#define HID   268
#define OUTD  128
#define NCEN  (BATCH*MCEN)     /* 16384 */
#define MAXROWS (NCEN*KNBR)    /* 524288 */
#define CAP   512
#define LN_EPS 1e-6f

// ---------------- device scratch (static; no allocations allowed) ----------
__device__ unsigned g_rowlist[MAXROWS];
__device__ int      g_nrows;
__device__ unsigned g_keys[NCEN*OUTD];

// Squared distance matching XLA's contracted lowering of sum((a-b)**2, -1):
// acc=0; acc=fma(dx,dx,acc); acc=fma(dy,dy,acc); acc=fma(dz,dz,acc)
// (fma with addend 0 == rn(dx*dx))
__device__ __forceinline__ float dist2e(float ax,float ay,float az,
                                        float bx,float by,float bz){
    float dx=__fadd_rn(ax,-bx);
    float dy=__fadd_rn(ay,-by);
    float dz=__fadd_rn(az,-bz);
    return __fmaf_rn(dz,dz,__fmaf_rn(dy,dy,__fmul_rn(dx,dx)));
}

__device__ __forceinline__ unsigned key_enc(float f){
    unsigned u=__float_as_uint(f);
    return (u&0x80000000u)? ~u : (u|0x80000000u);
}

// packed fp32x2 helpers (sm_103a packed FMA pipe)
__device__ __forceinline__ unsigned long long pk2(float lo, float hi){
    unsigned long long r;
    asm("mov.b64 %0, {%1, %2};" : "=l"(r) : "f"(lo), "f"(hi));
    return r;
}
__device__ __forceinline__ void ffma2(unsigned long long& d,
                                      unsigned long long a,
                                      unsigned long long b){
    asm("fma.rn.f32x2 %0, %1, %2, %0;" : "+l"(d) : "l"(a), "l"(b));
}

// ---------------- init -----------------------------------------------------
__global__ void init_kernel(){
    int idx = blockIdx.x*blockDim.x + threadIdx.x;
    if (idx==0) g_nrows=0;
    if (idx < NCEN*OUTD) g_keys[idx]=0u;   // 0 == minimum ordered key
}

// ---------------- FPS: one CTA per batch ------------------------------------
__global__ void fps_kernel(const float* __restrict__ x,
                           const int*   __restrict__ first_idx,
                           float*       __restrict__ centers){
    const int b = blockIdx.x;
    const float* xb = x + (size_t)b*NPTS*3;
    float* cb = centers + (size_t)b*MCEN*3;
    const int tid  = threadIdx.x;                // 512 threads
    const int lane = tid&31, wid = tid>>5;       // 16 warps
    const int PPT  = NPTS/512;                   // 16 points/thread
    __shared__ unsigned long long sk[2][16];
    float px[16],py[16],pz[16],d[16];
#pragma unroll
    for (int i=0;i<PPT;i++){
        int j = tid + i*512;
        px[i]=xb[j*3+0]; py[i]=xb[j*3+1]; pz[i]=xb[j*3+2];
    }
    int fi = first_idx[b];
    float fx=xb[fi*3+0], fy=xb[fi*3+1], fz=xb[fi*3+2];
    if (tid==0){ cb[0]=fx; cb[1]=fy; cb[2]=fz; }
    // init distances + fused argmax tracking (ties -> smallest index:
    // per-thread slots are ascending-index; strict > keeps the first)
    float bv=-1.0f; int bi=tid;
#pragma unroll
    for (int i=0;i<PPT;i++){
        d[i]=dist2e(px[i],py[i],pz[i],fx,fy,fz);
        if (d[i]>bv){ bv=d[i]; bi=tid+i*512; }
    }

    for (int s=1;s<MCEN;s++){
        // warp reduce: max d-bits (d>=0 so uint order == float order),
        // then min index among ties
        unsigned db = __float_as_uint(bv);
        unsigned m  = __reduce_max_sync(0xffffffffu, db);
        unsigned c  = (db==m)? (unsigned)bi : 0xffffu;
        unsigned wmin = __reduce_min_sync(0xffffffffu, c);
        int par = s&1;
        if (lane==0)
            sk[par][wid] = ((unsigned long long)m<<16) | (unsigned long long)(0xffffu - wmin);
        __syncthreads();
        // every thread tree-reduces the 16 packed partials (one barrier/step)
        unsigned long long t0,t1;
        unsigned long long v0=sk[par][0],v1=sk[par][1],v2=sk[par][2],v3=sk[par][3];
        unsigned long long v4=sk[par][4],v5=sk[par][5],v6=sk[par][6],v7=sk[par][7];
        unsigned long long v8=sk[par][8],v9=sk[par][9],va=sk[par][10],vb=sk[par][11];
        unsigned long long vc=sk[par][12],vd=sk[par][13],ve=sk[par][14],vf=sk[par][15];
        v0=v0>v8?v0:v8; v1=v1>v9?v1:v9; v2=v2>va?v2:va; v3=v3>vb?v3:vb;
        v4=v4>vc?v4:vc; v5=v5>vd?v5:vd; v6=v6>ve?v6:ve; v7=v7>vf?v7:vf;
        v0=v0>v4?v0:v4; v1=v1>v5?v1:v5; v2=v2>v6?v2:v6; v3=v3>v7?v3:v7;
        t0=v0>v2?v0:v2; t1=v1>v3?v1:v3;
        t0=t0>t1?t0:t1;
        int mi = 0xffff - (int)(t0 & 0xffffULL);
        fx=xb[mi*3+0]; fy=xb[mi*3+1]; fz=xb[mi*3+2];
        if (tid==0){ cb[s*3+0]=fx; cb[s*3+1]=fy; cb[s*3+2]=fz; }
        // fused: update distances AND compute next-step argmax in one pass
        bv=-1.0f; bi=tid;
#pragma unroll
        for (int i=0;i<PPT;i++){
            float nd=dist2e(px[i],py[i],pz[i],fx,fy,fz);
            float dn=fminf(d[i],nd);
            d[i]=dn;
            if (dn>bv){ bv=dn; bi=tid+i*512; }
        }
    }
}

// ---------------- ball query: one warp per center, smem-staged x ------------
// Selected set == K nearest within radius (exact stable-argsort ranks).
// Pads collapse to a single row with point index N-1 (JAX wraps -1 -> N-1).
#define BQ_CHUNK 1024
__global__ __launch_bounds__(256) void ballquery_kernel(
        const float* __restrict__ x, const float* __restrict__ centers){
    __shared__ float sx[BQ_CHUNK*3];
    __shared__ float sd2[8][CAP];
    __shared__ short sid[8][CAP];
    const int warp = threadIdx.x>>5, lane = threadIdx.x&31;
    const int cid = blockIdx.x*8 + warp;
    const int b = (blockIdx.x*8) >> 11;          // 2048 centers/batch, 8 | 2048
    const float* xb = x + (size_t)b*NPTS*3;
    float cx=centers[cid*3+0], cy=centers[cid*3+1], cz=centers[cid*3+2];
    int cnt=0;
    for (int c0=0;c0<NPTS;c0+=BQ_CHUNK){
        __syncthreads();
        for (int i=threadIdx.x;i<BQ_CHUNK*3;i+=256)
            sx[i]=xb[(size_t)c0*3+i];
        __syncthreads();
#pragma unroll 4
        for (int t=0;t<BQ_CHUNK/32;t++){
            int jj=t*32+lane;
            float d2=dist2e(sx[jj*3+0],sx[jj*3+1],sx[jj*3+2],cx,cy,cz);
            bool in = d2 < 0.09f;
            unsigned mk = __ballot_sync(0xffffffffu, in);
            int pos = cnt + __popc(mk & ((1u<<lane)-1u));
            if (in && pos<CAP){ sd2[warp][pos]=d2; sid[warp][pos]=(short)(c0+jj); }
            cnt += __popc(mk);
        }
    }
    if (cnt>CAP) cnt=CAP;
    __syncwarp();
    int nsel   = cnt<KNBR ? cnt : KNBR;
    int haspad = cnt<KNBR ? 1 : 0;
    int base=0;
    if (lane==0) base=atomicAdd(&g_nrows, nsel+haspad);
    base=__shfl_sync(0xffffffffu, base, 0);
    // rank select (candidate order == ascending point index -> stable argsort)
    for (int i=lane;i<cnt;i+=32){
        float di=sd2[warp][i];
        int rank=0;
        for (int j=0;j<cnt;j++){
            float dj=sd2[warp][j];
            rank += (dj<di) || (dj==di && j<i);
        }
        if (rank<KNBR)
            g_rowlist[base+rank]=((unsigned)cid<<13)|(unsigned)(unsigned short)sid[warp][i];
    }
    if (haspad && lane==0)
        g_rowlist[base+nsel]=((unsigned)cid<<13)|(unsigned)(NPTS-1);
}

// ---------------- fused MLP: gather -> GEMM1 -> gelu -> LN1 -> GEMM2 -> LN2
//                  -> per-center max via ordered-int atomicMax ---------------
#define HPAD1 288                      /* w1s row: 268 padded to 16*18 */
#define H1STR 68                       /* h1s row stride (16B-aligned rg*4) */
#define SMEM_W1F   (CINF*HPAD1)       /* 19296 floats */
#define SMEM_COMBF (CINF*64)          /* 4288 floats  */
#define SMEM_BYTES ((SMEM_W1F+SMEM_COMBF)*4)   /* 94336 B */

__global__ __launch_bounds__(256,2) void mlp_kernel(
    const float* __restrict__ x, const float* __restrict__ feat,
    const float* __restrict__ centers,
    const float* __restrict__ w1,const float* __restrict__ b1,
    const float* __restrict__ g1,const float* __restrict__ be1,
    const float* __restrict__ w2,const float* __restrict__ b2,
    const float* __restrict__ g2,const float* __restrict__ be2)
{
    extern __shared__ float smem[];
    float* w1s   = smem;                 // [67][288]
    float* combs = smem + SMEM_W1F;      // [67][64]   (A tile, k-major)
    float* h1s   = smem;                 // overlay w1s: [268][68]
    float* w2c   = combs;                // overlay combs: [32][128]

    const int nr = g_nrows;
    const int row0 = blockIdx.x*64;
    if (row0 >= nr) return;
    const int tid=threadIdx.x;
    const int rg=tid>>4, cg=tid&15;      // 16 rowgroups x 16 colgroups

    // stage w1 (row-major [67][268] -> padded [67][288], float4 moves)
    const float4* w1v=(const float4*)w1;
    for (int idx=tid; idx<67*67; idx+=256){
        int k=idx/67, c4=idx%67;
        *(float4*)&w1s[k*HPAD1 + c4*4] = w1v[idx];
    }
    // gather comb tile: comb[k][row], k<67  (feat | x - center)
    for (int idx=tid; idx<64*CINF; idx+=256){
        int lr=idx/CINF, k=idx%CINF;
        int gr=row0+lr; if (gr>=nr) gr=nr-1;
        unsigned e=g_rowlist[gr];
        int c = (int)(e>>13); int p = (int)(e & 8191);
        int bb = c>>11;
        float v;
        if (k<CFEAT) v = feat[((size_t)bb*NPTS+p)*CFEAT + k];
        else         v = x[((size_t)bb*NPTS+p)*3 + (k-CFEAT)] - centers[(size_t)c*3 + (k-CFEAT)];
        combs[k*64+lr]=v;
    }
    __syncthreads();

    // ---- GEMM1: 4 rows x 18 cols (9 f32x2 pairs) per thread ----------------
    // cg 0..14 cover cols 0..269 (clipped to 268); cg15 idle in epilogue.
    union { unsigned long long p[4][9]; float f[4][18]; } u;
#pragma unroll
    for (int r=0;r<4;r++)
#pragma unroll
        for (int jp=0;jp<9;jp++) u.p[r][jp]=0ULL;
    const int colbase=cg*18;
    for (int k=0;k<CINF;k++){
        float4 a=*(const float4*)&combs[k*64+rg*4];
        unsigned long long ap0=pk2(a.x,a.x), ap1=pk2(a.y,a.y);
        unsigned long long ap2=pk2(a.z,a.z), ap3=pk2(a.w,a.w);
        const unsigned long long* wr=(const unsigned long long*)&w1s[k*HPAD1+colbase];
#pragma unroll
        for (int jp=0;jp<9;jp++){
            unsigned long long w=wr[jp];
            ffma2(u.p[0][jp],ap0,w);
            ffma2(u.p[1][jp],ap1,w);
            ffma2(u.p[2][jp],ap2,w);
            ffma2(u.p[3][jp],ap3,w);
        }
    }

    int nv = HID - colbase;                    // valid cols this thread
    if (nv<0) nv=0; if (nv>18) nv=18;
    // bias + gelu (tanh form via exp identity; err ~1e-6) + LN1 stats
    float sum[4]={0,0,0,0}, sq[4]={0,0,0,0};
#pragma unroll
    for (int j=0;j<18;j++){
        if (j<nv){
            float bj=b1[colbase+j];
#pragma unroll
            for (int r=0;r<4;r++){
                float h=u.f[r][j]+bj;
                float z=0.7978845608028654f*(h+0.044715f*h*h*h);
                float e=__expf(2.0f*fminf(z,8.0f));
                float t=__fdividef(e-1.0f, e+1.0f);
                float g=0.5f*h*(1.0f+t);
                u.f[r][j]=g;
                sum[r]+=g; sq[r]=fmaf(g,g,sq[r]);
            }
        }
    }
#pragma unroll
    for (int off=1;off<16;off<<=1){
#pragma unroll
        for (int r=0;r<4;r++){
            sum[r]+=__shfl_xor_sync(0xffffffffu,sum[r],off);
            sq[r] +=__shfl_xor_sync(0xffffffffu,sq[r],off);
        }
    }
    float mu[4],rs[4];
#pragma unroll
    for (int r=0;r<4;r++){
        mu[r]=sum[r]*(1.0f/HID);
        float var=sq[r]*(1.0f/HID)-mu[r]*mu[r];
        rs[r]=rsqrtf(var+LN_EPS);
    }
    __syncthreads();          // everyone done with w1s/combs
    // write LN1 output into h1s[k][row] (stride 68: 16B-aligned row quads)
#pragma unroll
    for (int j=0;j<18;j++){
        if (j<nv){
            float gj=g1[colbase+j], bj=be1[colbase+j];
#pragma unroll
            for (int r=0;r<4;r++){
                float v=(u.f[r][j]-mu[r])*rs[r]*gj+bj;
                h1s[(colbase+j)*H1STR + rg*4 + r]=v;
            }
        }
    }
    __syncthreads();

    // ---- GEMM2: 4 rows x 8 cols (4 f32x2 pairs), w2 streamed in 32-k chunks
    union { unsigned long long p[4][4]; float f[4][8]; } v2;
#pragma unroll
    for (int r=0;r<4;r++)
#pragma unroll
        for (int c=0;c<4;c++) v2.p[r][c]=0ULL;
    const int ocol=cg*8;
    for (int kc=0;kc<HID;kc+=32){
        int kn = (HID-kc)<32 ? (HID-kc) : 32;
        for (int idx=tid; idx<kn*OUTD; idx+=256)
            w2c[idx]=w2[(size_t)kc*OUTD + idx];
        __syncthreads();
#pragma unroll 4
        for (int kk=0;kk<kn;kk++){
            float4 hv=*(const float4*)&h1s[(kc+kk)*H1STR + rg*4];
            unsigned long long h0=pk2(hv.x,hv.x), h1=pk2(hv.y,hv.y);
            unsigned long long h2=pk2(hv.z,hv.z), h3=pk2(hv.w,hv.w);
            const unsigned long long* wrp=(const unsigned long long*)&w2c[kk*OUTD+ocol];
            unsigned long long w0=wrp[0],w1p=wrp[1],w2p=wrp[2],w3p=wrp[3];
            ffma2(v2.p[0][0],h0,w0); ffma2(v2.p[0][1],h0,w1p);
            ffma2(v2.p[0][2],h0,w2p); ffma2(v2.p[0][3],h0,w3p);
            ffma2(v2.p[1][0],h1,w0); ffma2(v2.p[1][1],h1,w1p);
            ffma2(v2.p[1][2],h1,w2p); ffma2(v2.p[1][3],h1,w3p);
            ffma2(v2.p[2][0],h2,w0); ffma2(v2.p[2][1],h2,w1p);
            ffma2(v2.p[2][2],h2,w2p); ffma2(v2.p[2][3],h2,w3p);
            ffma2(v2.p[3][0],h3,w0); ffma2(v2.p[3][1],h3,w1p);
            ffma2(v2.p[3][2],h3,w2p); ffma2(v2.p[3][3],h3,w3p);
        }
        __syncthreads();
    }

    // bias2 + LN2 stats
    float sum2[4]={0,0,0,0}, sq2[4]={0,0,0,0};
#pragma unroll
    for (int c=0;c<8;c++){
        float bj=b2[ocol+c];
#pragma unroll
        for (int r=0;r<4;r++){
            float val=v2.f[r][c]+bj;
            v2.f[r][c]=val;
            sum2[r]+=val; sq2[r]=fmaf(val,val,sq2[r]);
        }
    }
#pragma unroll
    for (int off=1;off<16;off<<=1){
#pragma unroll
        for (int r=0;r<4;r++){
            sum2[r]+=__shfl_xor_sync(0xffffffffu,sum2[r],off);
            sq2[r] +=__shfl_xor_sync(0xffffffffu,sq2[r],off);
        }
    }
    float mu2[4],rs2[4];
#pragma unroll
    for (int r=0;r<4;r++){
        mu2[r]=sum2[r]*(1.0f/OUTD);
        float var=sq2[r]*(1.0f/OUTD)-mu2[r]*mu2[r];
        rs2[r]=rsqrtf(var+LN_EPS);
    }

    // row metadata for my 4 rows
    int rcid[4]; bool rval[4];
#pragma unroll
    for (int r=0;r<4;r++){
        int gr=row0+rg*4+r;
        rval[r]= gr<nr;
        unsigned e=g_rowlist[gr<nr?gr:(nr-1)];
        rcid[r]=(int)(e>>13);
    }
    // LN2 apply + run-merged atomicMax per output column
#pragma unroll
    for (int c=0;c<8;c++){
        float gj=g2[ocol+c], bj=be2[ocol+c];
        unsigned bk=0u; int bc=-1;
#pragma unroll
        for (int r=0;r<4;r++){
            if (!rval[r]) continue;
            float val=(v2.f[r][c]-mu2[r])*rs2[r]*gj+bj;
            unsigned k=key_enc(val);
            if (rcid[r]==bc){ bk = k>bk ? k : bk; }
            else{
                if (bc>=0) atomicMax(&g_keys[(size_t)bc*OUTD + ocol + c], bk);
                bc=rcid[r]; bk=k;
            }
        }
        if (bc>=0) atomicMax(&g_keys[(size_t)bc*OUTD + ocol + c], bk);
    }
}

// ---------------- finalize: decode ordered-int keys to floats ---------------
__global__ void finalize_kernel(float* __restrict__ out){
    int idx=blockIdx.x*blockDim.x+threadIdx.x;
    if (idx<NCEN*OUTD){
        unsigned k=g_keys[idx];
        unsigned u=(k&0x80000000u)? (k&0x7fffffffu) : ~k;
        out[idx]=__uint_as_float(u);
    }
}

// ---------------- launch -----------------------------------------------------
extern "C" void kernel_launch(void* const* d_in, const int* in_sizes, int n_in,
                              void* d_out, int out_size){
    const float* x    =(const float*)d_in[0];
    const float* feat =(const float*)d_in[1];
    const int*   fidx =(const int*)  d_in[2];
    const float* w1   =(const float*)d_in[3];
    const float* b1   =(const float*)d_in[4];
    const float* g1   =(const float*)d_in[5];
    const float* be1  =(const float*)d_in[6];
    const float* w2   =(const float*)d_in[7];
    const float* b2   =(const float*)d_in[8];
    const float* g2   =(const float*)d_in[9];
    const float* be2  =(const float*)d_in[10];
    float* outp=(float*)d_out;
    float* centers = outp;                       // [B*M*3]
    float* result  = outp + (size_t)NCEN*3;      // [B*M*128]

    cudaFuncSetAttribute(mlp_kernel,
        cudaFuncAttributeMaxDynamicSharedMemorySize, SMEM_BYTES);

    init_kernel<<<4096,512>>>();
    fps_kernel<<<BATCH,512>>>(x, fidx, centers);
    ballquery_kernel<<<NCEN/8,256>>>(x, centers);
    mlp_kernel<<<MAXROWS/64,256,SMEM_BYTES>>>(x, feat, centers,
                                              w1,b1,g1,be1,w2,b2,g2,be2);
    finalize_kernel<<<4096,512>>>(result);
}

// round 9
// speedup vs baseline: 1.1005x; 1.1005x over previous
#include <cuda_runtime.h>
#include <cstdint>

#define BATCH 8
#define NPTS  8192
#define MCEN  2048
#define KNBR  32
#define CFEAT 64
#define CINF  67
#define HID   268
#define OUTD  128
#define NCEN  (BATCH*MCEN)
#define CAPM  256
#define LN_EPS 1e-6f

__device__ int g_prog[BATCH];

// Squared distance matching XLA's contracted lowering of sum((a-b)**2, -1)
__device__ __forceinline__ float dist2e(float ax,float ay,float az,
                                        float bx,float by,float bz){
    float dx=__fadd_rn(ax,-bx);
    float dy=__fadd_rn(ay,-by);
    float dz=__fadd_rn(az,-bz);
    return __fmaf_rn(dz,dz,__fmaf_rn(dy,dy,__fmul_rn(dx,dx)));
}

// L1-bypassing load (always L2-fresh) for producer/consumer data
__device__ __forceinline__ float ldcv(const float* p){
    float v;
    asm volatile("ld.global.cv.f32 %0, [%1];" : "=f"(v) : "l"(p) : "memory");
    return v;
}

// packed fp32x2 helpers (per-lane IEEE identical to scalar ops)
__device__ __forceinline__ unsigned long long pk2(float lo, float hi){
    unsigned long long r;
    asm("mov.b64 %0, {%1, %2};" : "=l"(r) : "f"(lo), "f"(hi));
    return r;
}
__device__ __forceinline__ void unpk(unsigned long long v, float& lo, float& hi){
    asm("mov.b64 {%0, %1}, %2;" : "=f"(lo), "=f"(hi) : "l"(v));
}
__device__ __forceinline__ unsigned long long add2(unsigned long long a, unsigned long long b){
    unsigned long long r;
    asm("add.rn.f32x2 %0, %1, %2;" : "=l"(r) : "l"(a), "l"(b));
    return r;
}
__device__ __forceinline__ unsigned long long mul2(unsigned long long a, unsigned long long b){
    unsigned long long r;
    asm("mul.rn.f32x2 %0, %1, %2;" : "=l"(r) : "l"(a), "l"(b));
    return r;
}
__device__ __forceinline__ void ffma2(unsigned long long& d,
                                      unsigned long long a,
                                      unsigned long long b){
    asm("fma.rn.f32x2 %0, %1, %2, %0;" : "+l"(d) : "l"(a), "l"(b));
}

// ---------------- init: zero progress counters ------------------------------
__global__ void initp_kernel(){
    if (threadIdx.x < BATCH) g_prog[threadIdx.x]=0;
}

// ---------------- FPS: one CTA per batch, 1024 threads ----------------------
__global__ __launch_bounds__(1024,1) void fps_kernel(const float* __restrict__ x,
                           const int*   __restrict__ first_idx,
                           float*       __restrict__ centers){
    const int b = blockIdx.x;
    const float* xb = x + (size_t)b*NPTS*3;
    float* cb = centers + (size_t)b*MCEN*3;
    const int tid  = threadIdx.x;                // 1024 threads
    const int lane = tid&31, wid = tid>>5;       // 32 warps
    __shared__ unsigned long long sk[32];
    __shared__ unsigned long long swin;

    // allow dependent (fused) kernel to launch immediately
    asm volatile("griddepcontrol.launch_dependents;" ::: "memory");

    unsigned long long pxp[4],pyp[4],pzp[4];
    float d[8];
    float fx,fy,fz; float bv; int bi;
    {
        float px[8],py[8],pz[8];
#pragma unroll
        for (int i=0;i<8;i++){
            int j = tid + i*1024;
            px[i]=xb[j*3+0]; py[i]=xb[j*3+1]; pz[i]=xb[j*3+2];
        }
        int fi = first_idx[b];
        fx=xb[fi*3+0]; fy=xb[fi*3+1]; fz=xb[fi*3+2];
        if (tid==0){ cb[0]=fx; cb[1]=fy; cb[2]=fz; }
        bv=-1.0f; bi=tid;
#pragma unroll
        for (int i=0;i<8;i++){
            d[i]=dist2e(px[i],py[i],pz[i],fx,fy,fz);
            if (d[i]>bv){ bv=d[i]; bi=tid+i*1024; }
        }
#pragma unroll
        for (int i=0;i<4;i++){
            pxp[i]=pk2(px[2*i],px[2*i+1]);
            pyp[i]=pk2(py[2*i],py[2*i+1]);
            pzp[i]=pk2(pz[2*i],pz[2*i+1]);
        }
    }

    for (int s=1;s<MCEN;s++){
        // warp reduce: max d-bits (d>=0 so uint order == float order),
        // then min index among ties (global first-index tie-break)
        unsigned db = __float_as_uint(bv);
        unsigned m  = __reduce_max_sync(0xffffffffu, db);
        unsigned c  = (db==m)? (unsigned)bi : 0xffffu;
        unsigned wmin = __reduce_min_sync(0xffffffffu, c);
        if (lane==0)
            sk[wid] = ((unsigned long long)m<<16) | (unsigned long long)(0xffffu - wmin);
        __syncthreads();
        if (wid==0){
            unsigned long long k = sk[lane];
#pragma unroll
            for (int off=16;off>0;off>>=1){
                unsigned long long o=__shfl_xor_sync(0xffffffffu,k,off);
                if (o>k) k=o;
            }
            if (lane==0) swin=k;
        }
        __syncthreads();
        int mi = 0xffff - (int)(swin & 0xffffULL);
        fx=xb[mi*3+0]; fy=xb[mi*3+1]; fz=xb[mi*3+2];
        if (tid==0){
            cb[s*3+0]=fx; cb[s*3+1]=fy; cb[s*3+2]=fz;
            if (s&1){
                int pv=s+1;
                asm volatile("st.release.gpu.s32 [%0], %1;"
                             :: "l"(&g_prog[b]), "r"(pv) : "memory");
            }
        }
        unsigned long long nfx=pk2(-fx,-fx), nfy=pk2(-fy,-fy), nfz=pk2(-fz,-fz);
        bv=-1.0f; bi=tid;
#pragma unroll
        for (int i=0;i<4;i++){
            unsigned long long dx=add2(pxp[i],nfx);
            unsigned long long dy=add2(pyp[i],nfy);
            unsigned long long dz=add2(pzp[i],nfz);
            unsigned long long s2=mul2(dx,dx);
            ffma2(s2,dy,dy);
            ffma2(s2,dz,dz);
            float lo,hi; unpk(s2,lo,hi);
            float d0=fminf(d[2*i],lo);   d[2*i]=d0;
            if (d0>bv){ bv=d0; bi=tid+(2*i)*1024; }
            float d1=fminf(d[2*i+1],hi); d[2*i+1]=d1;
            if (d1>bv){ bv=d1; bi=tid+(2*i+1)*1024; }
        }
    }
}

// ---------------- fused: ballquery + MLP + max, one CTA per 2 centers -------
#define HPAD1 288
#define H1STR 68
#define SMEM_W1F   (CINF*HPAD1)               /* 19296 floats */
#define SMEM_COMBF (CINF*64)                  /* 4288 floats  */
#define SMEM_MAINF (SMEM_W1F+SMEM_COMBF)      /* 23584 floats */
#define SMEM_BYTES (SMEM_MAINF*4 + 256)

__global__ __launch_bounds__(256,2) void fused_kernel(
    const float* __restrict__ x, const float* __restrict__ feat,
    const float* __restrict__ centers,
    const float* __restrict__ w1,const float* __restrict__ b1,
    const float* __restrict__ g1,const float* __restrict__ be1,
    const float* __restrict__ w2,const float* __restrict__ b2,
    const float* __restrict__ g2,const float* __restrict__ be2,
    float* __restrict__ result)
{
    extern __shared__ float smem[];
    float* w1s   = smem;                 // [67][288]
    float* combs = smem + SMEM_W1F;      // [67][64]
    float* h1s   = smem;                 // overlay: [268][68]
    float* w2c   = combs;                // overlay: [32][128]
    // ballquery-phase overlays (inside w1s region, dead at that time)
    float* sx   = smem;                  // 3072 floats (1024 pts)
    float* cd2  = smem + 3072;           // [2][256]
    short* cidx = (short*)(smem + 3584); // [2][256]
    int*   ccnt = (int*)(smem + 3840);   // [2]
    // persistent tail region (never overlaid)
    short* rowpt = (short*)(smem + SMEM_MAINF);   // [64]
    int*   vrows = (int*)(smem + SMEM_MAINF + 32);// [2]

    const int tid=threadIdx.x;
    const int sp = blockIdx.x>>3, b = blockIdx.x&7;
    const int cidA = b*MCEN + 2*sp, cidB = cidA+1;
    const float* xb = x + (size_t)b*NPTS*3;

    if (tid==0){
        ccnt[0]=0; ccnt[1]=0;
        int target = 2*sp+2, v;
        do {
            asm volatile("ld.acquire.gpu.s32 %0, [%1];"
                         : "=r"(v) : "l"(&g_prog[b]) : "memory");
            if (v<target) __nanosleep(128);
        } while (v<target);
        // invalidate this SM's L1 (fence scope >= cluster emits CCTL.IVALL):
        // L1 lines of `centers` cached by earlier CTAs on this SM may predate
        // FPS's writes; L1 persists across CTAs within a launch.
        __threadfence();
    }
    __syncthreads();

    // belt-and-suspenders: read centers with ld.global.cv (L1-bypass, always
    // L2-fresh; L2 is coherent with FPS's release-ordered stores)
    float cAx=ldcv(&centers[cidA*3+0]), cAy=ldcv(&centers[cidA*3+1]), cAz=ldcv(&centers[cidA*3+2]);
    float cBx=ldcv(&centers[cidB*3+0]), cBy=ldcv(&centers[cidB*3+1]), cBz=ldcv(&centers[cidB*3+2]);

    // ---- ball query: warps 0-3 -> center A, 4-7 -> center B ----------------
    const int warp=tid>>5, lane=tid&31;
    const int sel=warp>>2, q=warp&3;
    const float cx = sel? cBx:cAx, cy = sel? cBy:cAy, cz = sel? cBz:cAz;
    for (int c0=0;c0<NPTS;c0+=1024){
        __syncthreads();
        for (int i=tid;i<3072;i+=256) sx[i]=xb[(size_t)c0*3+i];
        __syncthreads();
#pragma unroll
        for (int t=0;t<8;t++){
            int jj=q*256+t*32+lane;
            float d2=dist2e(sx[jj*3+0],sx[jj*3+1],sx[jj*3+2],cx,cy,cz);
            bool in = d2 < 0.09f;
            unsigned mk=__ballot_sync(0xffffffffu,in);
            int n=__popc(mk);
            if (n){
                int basep=0;
                if (lane==0) basep=atomicAdd(&ccnt[sel],n);
                basep=__shfl_sync(0xffffffffu,basep,0);
                int pos=basep+__popc(mk&((1u<<lane)-1u));
                if (in && pos<CAPM){
                    cd2[sel*CAPM+pos]=d2;
                    cidx[sel*CAPM+pos]=(short)(c0+jj);
                }
            }
        }
    }
    __syncthreads();

    // ---- rank select: exact stable-argsort top-32 per center ---------------
    {
        int s2=tid>>7;
        int cnt=ccnt[s2]; if (cnt>CAPM) cnt=CAPM;
        int nselc = cnt<KNBR ? cnt : KNBR;
        int haspad = cnt<KNBR ? 1 : 0;
        if ((tid&127)==0) vrows[s2]=nselc+haspad;
        for (int i=tid&127;i<cnt;i+=128){
            float di=cd2[s2*CAPM+i]; int idi=cidx[s2*CAPM+i];
            int rank=0;
            for (int j=0;j<cnt;j++){
                float dj=cd2[s2*CAPM+j];
                rank += (dj<di) || (dj==di && cidx[s2*CAPM+j]<idi);
            }
            if (rank<KNBR) rowpt[s2*32+rank]=(short)idi;
        }
        // pad row (JAX wraps -1 -> N-1) + finite dummies for masked rows
        for (int r=tid&127;r<KNBR;r+=128)
            if (r>=nselc) rowpt[s2*32+r]=(short)(NPTS-1);
    }
    __syncthreads();

    // ---- stage w1 (padded) + gather comb -----------------------------------
    const float4* w1v=(const float4*)w1;
    for (int idx=tid; idx<67*67; idx+=256){
        int k=idx/67, c4=idx%67;
        *(float4*)&w1s[k*HPAD1 + c4*4] = w1v[idx];
    }
    for (int idx=tid; idx<67*20; idx+=256){
        int k=idx/20, c=idx%20;
        w1s[k*HPAD1 + 268 + c]=0.0f;
    }
    for (int idx=tid; idx<64*CINF; idx+=256){
        int lr=idx/CINF, k=idx%CINF;
        int p=rowpt[lr];
        float v;
        if (k<CFEAT) v = feat[((size_t)b*NPTS+p)*CFEAT + k];
        else{
            float pc = x[((size_t)b*NPTS+p)*3 + (k-CFEAT)];
            float cc = (lr<32) ? ((k==64)?cAx:(k==65)?cAy:cAz)
                               : ((k==64)?cBx:(k==65)?cBy:cBz);
            v = pc - cc;
        }
        combs[k*64+lr]=v;
    }
    __syncthreads();

    // ---- GEMM1: 4 rows x 18 cols (9 f32x2 pairs) per thread ----------------
    union { unsigned long long p[4][9]; float f[4][18]; } u;
#pragma unroll
    for (int r=0;r<4;r++)
#pragma unroll
        for (int jp=0;jp<9;jp++) u.p[r][jp]=0ULL;
    const int rg=tid>>4, cg=tid&15;
    const int colbase=cg*18;
    for (int k=0;k<CINF;k++){
        float4 a=*(const float4*)&combs[k*64+rg*4];
        unsigned long long ap0=pk2(a.x,a.x), ap1=pk2(a.y,a.y);
        unsigned long long ap2=pk2(a.z,a.z), ap3=pk2(a.w,a.w);
        const unsigned long long* wr=(const unsigned long long*)&w1s[k*HPAD1+colbase];
#pragma unroll
        for (int jp=0;jp<9;jp++){
            unsigned long long w=wr[jp];
            ffma2(u.p[0][jp],ap0,w);
            ffma2(u.p[1][jp],ap1,w);
            ffma2(u.p[2][jp],ap2,w);
            ffma2(u.p[3][jp],ap3,w);
        }
    }

    int nv = HID - colbase;
    if (nv<0) nv=0; if (nv>18) nv=18;
    float sum[4]={0,0,0,0}, sq[4]={0,0,0,0};
#pragma unroll
    for (int j=0;j<18;j++){
        if (j<nv){
            float bj=b1[colbase+j];
#pragma unroll
            for (int r=0;r<4;r++){
                float h=u.f[r][j]+bj;
                float z=0.7978845608028654f*(h+0.044715f*h*h*h);
                float e=__expf(2.0f*fminf(z,8.0f));
                float t=__fdividef(e-1.0f, e+1.0f);
                float g=0.5f*h*(1.0f+t);
                u.f[r][j]=g;
                sum[r]+=g; sq[r]=fmaf(g,g,sq[r]);
            }
        }
    }
#pragma unroll
    for (int off=1;off<16;off<<=1){
#pragma unroll
        for (int r=0;r<4;r++){
            sum[r]+=__shfl_xor_sync(0xffffffffu,sum[r],off);
            sq[r] +=__shfl_xor_sync(0xffffffffu,sq[r],off);
        }
    }
    float mu[4],rs[4];
#pragma unroll
    for (int r=0;r<4;r++){
        mu[r]=sum[r]*(1.0f/HID);
        float var=sq[r]*(1.0f/HID)-mu[r]*mu[r];
        rs[r]=rsqrtf(var+LN_EPS);
    }
    __syncthreads();
#pragma unroll
    for (int j=0;j<18;j++){
        if (j<nv){
            float gj=g1[colbase+j], bj=be1[colbase+j];
#pragma unroll
            for (int r=0;r<4;r++){
                float v=(u.f[r][j]-mu[r])*rs[r]*gj+bj;
                h1s[(colbase+j)*H1STR + rg*4 + r]=v;
            }
        }
    }
    __syncthreads();

    // ---- GEMM2: 4 rows x 8 cols, w2 streamed in 32-k chunks ----------------
    union { unsigned long long p[4][4]; float f[4][8]; } v2;
#pragma unroll
    for (int r=0;r<4;r++)
#pragma unroll
        for (int c=0;c<4;c++) v2.p[r][c]=0ULL;
    const int ocol=cg*8;
    for (int kc=0;kc<HID;kc+=32){
        int kn = (HID-kc)<32 ? (HID-kc) : 32;
        for (int idx=tid; idx<kn*OUTD; idx+=256)
            w2c[idx]=w2[(size_t)kc*OUTD + idx];
        __syncthreads();
#pragma unroll 4
        for (int kk=0;kk<kn;kk++){
            float4 hv=*(const float4*)&h1s[(kc+kk)*H1STR + rg*4];
            unsigned long long h0=pk2(hv.x,hv.x), h1=pk2(hv.y,hv.y);
            unsigned long long h2=pk2(hv.z,hv.z), h3=pk2(hv.w,hv.w);
            const unsigned long long* wrp=(const unsigned long long*)&w2c[kk*OUTD+ocol];
            unsigned long long w0=wrp[0],w1p=wrp[1],w2p=wrp[2],w3p=wrp[3];
            ffma2(v2.p[0][0],h0,w0); ffma2(v2.p[0][1],h0,w1p);
            ffma2(v2.p[0][2],h0,w2p); ffma2(v2.p[0][3],h0,w3p);
            ffma2(v2.p[1][0],h1,w0); ffma2(v2.p[1][1],h1,w1p);
            ffma2(v2.p[1][2],h1,w2p); ffma2(v2.p[1][3],h1,w3p);
            ffma2(v2.p[2][0],h2,w0); ffma2(v2.p[2][1],h2,w1p);
            ffma2(v2.p[2][2],h2,w2p); ffma2(v2.p[2][3],h2,w3p);
            ffma2(v2.p[3][0],h3,w0); ffma2(v2.p[3][1],h3,w1p);
            ffma2(v2.p[3][2],h3,w2p); ffma2(v2.p[3][3],h3,w3p);
        }
        __syncthreads();
    }

    // ---- bias2 + LN2 --------------------------------------------------------
    float sum2[4]={0,0,0,0}, sq2[4]={0,0,0,0};
#pragma unroll
    for (int c=0;c<8;c++){
        float bj=b2[ocol+c];
#pragma unroll
        for (int r=0;r<4;r++){
            float val=v2.f[r][c]+bj;
            v2.f[r][c]=val;
            sum2[r]+=val; sq2[r]=fmaf(val,val,sq2[r]);
        }
    }
#pragma unroll
    for (int off=1;off<16;off<<=1){
#pragma unroll
        for (int r=0;r<4;r++){
            sum2[r]+=__shfl_xor_sync(0xffffffffu,sum2[r],off);
            sq2[r] +=__shfl_xor_sync(0xffffffffu,sq2[r],off);
        }
    }
    float mu2[4],rs2[4];
#pragma unroll
    for (int r=0;r<4;r++){
        mu2[r]=sum2[r]*(1.0f/OUTD);
        float var=sq2[r]*(1.0f/OUTD)-mu2[r]*mu2[r];
        rs2[r]=rsqrtf(var+LN_EPS);
    }

    // ---- LN2 apply + in-CTA max over valid rows ----------------------------
    const float NEGINF=__int_as_float(0xff800000);
    const int vA=vrows[0], vB=vrows[1];
    float* red = combs;                 // 2048 floats, w2c dead now
#pragma unroll
    for (int c=0;c<8;c++){
        float gj=g2[ocol+c], bj=be2[ocol+c];
        float best=NEGINF;
#pragma unroll
        for (int r=0;r<4;r++){
            int lr=rg*4+r;
            bool ok = (lr<32)? (lr<vA) : (lr-32<vB);
            if (ok){
                float val=(v2.f[r][c]-mu2[r])*rs2[r]*gj+bj;
                best=fmaxf(best,val);
            }
        }
        red[(rg*16+cg)*8+c]=best;
    }
    __syncthreads();
    {
        int s2=tid>>7, cg2=(tid>>3)&15, c2=tid&7;
        float m=NEGINF;
#pragma unroll
        for (int r2=0;r2<8;r2++)
            m=fmaxf(m, red[((s2*8+r2)*16+cg2)*8+c2]);
        int cid = s2? cidB:cidA;
        result[(size_t)cid*OUTD + cg2*8 + c2]=m;
    }
}

// ---------------- launch -----------------------------------------------------
extern "C" void kernel_launch(void* const* d_in, const int* in_sizes, int n_in,
                              void* d_out, int out_size){
    const float* x    =(const float*)d_in[0];
    const float* feat =(const float*)d_in[1];
    const int*   fidx =(const int*)  d_in[2];
    const float* w1   =(const float*)d_in[3];
    const float* b1   =(const float*)d_in[4];
    const float* g1   =(const float*)d_in[5];
    const float* be1  =(const float*)d_in[6];
    const float* w2   =(const float*)d_in[7];
    const float* b2   =(const float*)d_in[8];
    const float* g2   =(const float*)d_in[9];
    const float* be2  =(const float*)d_in[10];
    float* outp=(float*)d_out;
    float* centers = outp;                       // [B*M*3]
    float* result  = outp + (size_t)NCEN*3;      // [B*M*128]

    cudaFuncSetAttribute(fused_kernel,
        cudaFuncAttributeMaxDynamicSharedMemorySize, SMEM_BYTES);

    initp_kernel<<<1,32>>>();
    fps_kernel<<<BATCH,1024>>>(x, fidx, centers);

    // fused kernel: PDL-launched so it overlaps FPS, gated by g_prog flags
    cudaLaunchConfig_t cfg = {};
    cfg.gridDim  = dim3(NCEN/2, 1, 1);
    cfg.blockDim = dim3(256, 1, 1);
    cfg.dynamicSmemBytes = SMEM_BYTES;
    cfg.stream = 0;
    cudaLaunchAttribute attrs[1];
    attrs[0].id = cudaLaunchAttributeProgrammaticStreamSerialization;
    attrs[0].val.programmaticStreamSerializationAllowed = 1;
    cfg.attrs = attrs;
    cfg.numAttrs = 1;
    cudaLaunchKernelEx(&cfg, fused_kernel, x, feat, (const float*)centers,
                       w1,b1,g1,be1,w2,b2,g2,be2, result);
}